// round 3
// baseline (speedup 1.0000x reference)
#include <cuda_runtime.h>
#include <math.h>

#define NN 50000
#define EE 1600000
#define GG 64
#define ETOT (EE + NN)   // 1650000

// ---------------- device scratch ----------------
__device__ __align__(16) float g_loop_s[NN];
__device__ __align__(16) float g_loop_c[NN];
__device__ __align__(16) float g_loop_attr[NN];
__device__ __align__(16) float g_xl[NN * 64];
__device__ __align__(16) float g_xr[NN * 64];
__device__ __align__(16) float g_accum[NN * 64];
__device__ __align__(16) float g_denom[NN];
__device__ __align__(16) float g_gsum[GG * 64];
__device__ float          g_gcnt[GG];

// ---------------- init ----------------
__global__ void k_init0() {
    int i = blockIdx.x * blockDim.x + threadIdx.x;
    if (i < NN) { g_loop_s[i] = 0.f; g_loop_c[i] = 0.f; }
    if (i < GG * 64) g_gsum[i] = 0.f;
    if (i < GG) g_gcnt[i] = 0.f;
}

// ---------------- self-loop attr (fill_value='mean') ----------------
__global__ void k_loopsum(const int* __restrict__ dst, const float* __restrict__ ea) {
    int e = blockIdx.x * blockDim.x + threadIdx.x;
    if (e >= EE) return;
    int d = dst[e];
    atomicAdd(&g_loop_s[d], ea[e]);
    atomicAdd(&g_loop_c[d], 1.f);
}

__global__ void k_loopattr() {
    int n = blockIdx.x * blockDim.x + threadIdx.x;
    if (n >= NN) return;
    g_loop_attr[n] = g_loop_s[n] / fmaxf(g_loop_c[n], 1.f);
}

// ---------------- fused dual GEMM: xl = f(X)@Wl+bl, xr = f(X)@Wr+br --------------
// 256 threads, 64 nodes/block. X tile AND both weight matrices staged in SMEM.
// FUSE_ELU: reconstruct h = ELU(accum/denom + ebias) instead of reading Xg.
// Epilogue also zeroes g_accum/g_denom for this block's rows (next layer's scatter).
template <int K, int FUSE_ELU>
__global__ __launch_bounds__(256) void k_gemm2(
        const float* __restrict__ Xg,
        const float* __restrict__ Wl, const float* __restrict__ bl,
        const float* __restrict__ Wr, const float* __restrict__ br,
        const float* __restrict__ ebias) {
    extern __shared__ float sh[];
    float* Wls = sh;                 // K*64
    float* Wrs = sh + K * 64;        // K*64
    float* Xs  = sh + 2 * K * 64;    // 64*K

    int t = threadIdx.x;
    int base = blockIdx.x * 64;

    // stage weights (coalesced float4)
    for (int i = t; i < K * 16; i += 256) {
        *(float4*)&Wls[i * 4] = __ldg((const float4*)&Wl[i * 4]);
        *(float4*)&Wrs[i * 4] = __ldg((const float4*)&Wr[i * 4]);
    }
    // stage X tile
    const int K4 = K / 4;
    for (int i = t; i < 64 * K4; i += 256) {
        int row = i / K4, c4 = i - row * K4;
        int node = base + row;
        float4 v = make_float4(0.f, 0.f, 0.f, 0.f);
        if (node < NN) {
            if (FUSE_ELU) {
                float4 a = *(const float4*)&g_accum[(size_t)node * 64 + c4 * 4];
                float inv = 1.f / (g_denom[node] + 1e-16f);
                float4 b = __ldg((const float4*)&ebias[c4 * 4]);
                v.x = a.x * inv + b.x;  v.x = v.x > 0.f ? v.x : expm1f(v.x);
                v.y = a.y * inv + b.y;  v.y = v.y > 0.f ? v.y : expm1f(v.y);
                v.z = a.z * inv + b.z;  v.z = v.z > 0.f ? v.z : expm1f(v.z);
                v.w = a.w * inv + b.w;  v.w = v.w > 0.f ? v.w : expm1f(v.w);
            } else {
                v = __ldg((const float4*)&Xg[(size_t)node * K + c4 * 4]);
            }
        }
        *(float4*)&Xs[row * K + c4 * 4] = v;
    }
    __syncthreads();

    int cg = t & 15;            // 4 output channels
    int ng = t >> 4;            // 4 nodes
    int nb = base + ng * 4;

    float4 bl4 = __ldg((const float4*)&bl[cg * 4]);
    float4 br4 = __ldg((const float4*)&br[cg * 4]);
    float4 l0 = bl4, l1 = bl4, l2 = bl4, l3 = bl4;
    float4 r0 = br4, r1 = br4, r2 = br4, r3 = br4;

    const float* xs0 = &Xs[(ng * 4 + 0) * K];
    const float* xs1 = &Xs[(ng * 4 + 1) * K];
    const float* xs2 = &Xs[(ng * 4 + 2) * K];
    const float* xs3 = &Xs[(ng * 4 + 3) * K];

#pragma unroll 2
    for (int k = 0; k < K; k += 4) {
        float4 wl0 = *(float4*)&Wls[(k + 0) * 64 + cg * 4];
        float4 wl1 = *(float4*)&Wls[(k + 1) * 64 + cg * 4];
        float4 wl2 = *(float4*)&Wls[(k + 2) * 64 + cg * 4];
        float4 wl3 = *(float4*)&Wls[(k + 3) * 64 + cg * 4];
        float4 wr0 = *(float4*)&Wrs[(k + 0) * 64 + cg * 4];
        float4 wr1 = *(float4*)&Wrs[(k + 1) * 64 + cg * 4];
        float4 wr2 = *(float4*)&Wrs[(k + 2) * 64 + cg * 4];
        float4 wr3 = *(float4*)&Wrs[(k + 3) * 64 + cg * 4];
        float4 xa = *(const float4*)(xs0 + k);
        float4 xb = *(const float4*)(xs1 + k);
        float4 xc = *(const float4*)(xs2 + k);
        float4 xd = *(const float4*)(xs3 + k);
#define ACC8(L, R, xq)                                                  \
        L.x = fmaf(xq.x, wl0.x, L.x); L.y = fmaf(xq.x, wl0.y, L.y);     \
        L.z = fmaf(xq.x, wl0.z, L.z); L.w = fmaf(xq.x, wl0.w, L.w);     \
        L.x = fmaf(xq.y, wl1.x, L.x); L.y = fmaf(xq.y, wl1.y, L.y);     \
        L.z = fmaf(xq.y, wl1.z, L.z); L.w = fmaf(xq.y, wl1.w, L.w);     \
        L.x = fmaf(xq.z, wl2.x, L.x); L.y = fmaf(xq.z, wl2.y, L.y);     \
        L.z = fmaf(xq.z, wl2.z, L.z); L.w = fmaf(xq.z, wl2.w, L.w);     \
        L.x = fmaf(xq.w, wl3.x, L.x); L.y = fmaf(xq.w, wl3.y, L.y);     \
        L.z = fmaf(xq.w, wl3.z, L.z); L.w = fmaf(xq.w, wl3.w, L.w);     \
        R.x = fmaf(xq.x, wr0.x, R.x); R.y = fmaf(xq.x, wr0.y, R.y);     \
        R.z = fmaf(xq.x, wr0.z, R.z); R.w = fmaf(xq.x, wr0.w, R.w);     \
        R.x = fmaf(xq.y, wr1.x, R.x); R.y = fmaf(xq.y, wr1.y, R.y);     \
        R.z = fmaf(xq.y, wr1.z, R.z); R.w = fmaf(xq.y, wr1.w, R.w);     \
        R.x = fmaf(xq.z, wr2.x, R.x); R.y = fmaf(xq.z, wr2.y, R.y);     \
        R.z = fmaf(xq.z, wr2.z, R.z); R.w = fmaf(xq.z, wr2.w, R.w);     \
        R.x = fmaf(xq.w, wr3.x, R.x); R.y = fmaf(xq.w, wr3.y, R.y);     \
        R.z = fmaf(xq.w, wr3.z, R.z); R.w = fmaf(xq.w, wr3.w, R.w);
        ACC8(l0, r0, xa) ACC8(l1, r1, xb) ACC8(l2, r2, xc) ACC8(l3, r3, xd)
#undef ACC8
    }
    const float4 z4 = make_float4(0.f, 0.f, 0.f, 0.f);
    if (nb + 0 < NN) { *(float4*)&g_xl[(size_t)(nb + 0) * 64 + cg * 4] = l0;
                       *(float4*)&g_xr[(size_t)(nb + 0) * 64 + cg * 4] = r0;
                       *(float4*)&g_accum[(size_t)(nb + 0) * 64 + cg * 4] = z4; }
    if (nb + 1 < NN) { *(float4*)&g_xl[(size_t)(nb + 1) * 64 + cg * 4] = l1;
                       *(float4*)&g_xr[(size_t)(nb + 1) * 64 + cg * 4] = r1;
                       *(float4*)&g_accum[(size_t)(nb + 1) * 64 + cg * 4] = z4; }
    if (nb + 2 < NN) { *(float4*)&g_xl[(size_t)(nb + 2) * 64 + cg * 4] = l2;
                       *(float4*)&g_xr[(size_t)(nb + 2) * 64 + cg * 4] = r2;
                       *(float4*)&g_accum[(size_t)(nb + 2) * 64 + cg * 4] = z4; }
    if (nb + 3 < NN) { *(float4*)&g_xl[(size_t)(nb + 3) * 64 + cg * 4] = l3;
                       *(float4*)&g_xr[(size_t)(nb + 3) * 64 + cg * 4] = r3;
                       *(float4*)&g_accum[(size_t)(nb + 3) * 64 + cg * 4] = z4; }
    if (t < 64 && base + t < NN) g_denom[base + t] = 0.f;
}

// ---------------- fused edge pass (softmax shift-invariant: no segment-max) ----------
// 8 threads/edge, 32 edges/block: gather xl[src], xr[dst] (2 float4 each);
// leakyrelu; logit; p = exp(logit); scatter p*xl[src] + p.
__global__ __launch_bounds__(256) void k_edge(
        const int* __restrict__ src, const int* __restrict__ dst,
        const float* __restrict__ eattr,
        const float* __restrict__ We, const float* __restrict__ att) {
    int t = threadIdx.x;
    int e = blockIdx.x * 32 + (t >> 3);
    int cg = t & 7;                       // 8 channels: [cg*8, cg*8+8)
    bool valid = e < ETOT;
    if (!valid) e = ETOT - 1;             // clamp; keep warp intact for shfl

    int s, d; float ea;
    if (e < EE) { s = src[e]; d = dst[e]; ea = eattr[e]; }
    else        { s = d = e - EE; ea = g_loop_attr[e - EE]; }

    const float* xlp = &g_xl[(size_t)s * 64 + cg * 8];
    const float* xrp = &g_xr[(size_t)d * 64 + cg * 8];
    float4 a0 = *(const float4*)(xlp);
    float4 a1 = *(const float4*)(xlp + 4);
    float4 b0 = *(const float4*)(xrp);
    float4 b1 = *(const float4*)(xrp + 4);
    float4 w0 = __ldg((const float4*)&We[cg * 8]);
    float4 w1 = __ldg((const float4*)&We[cg * 8 + 4]);
    float4 at0 = __ldg((const float4*)&att[cg * 8]);
    float4 at1 = __ldg((const float4*)&att[cg * 8 + 4]);

    float v0 = a0.x + b0.x + ea * w0.x;  v0 = v0 > 0.f ? v0 : 0.2f * v0;
    float v1 = a0.y + b0.y + ea * w0.y;  v1 = v1 > 0.f ? v1 : 0.2f * v1;
    float v2 = a0.z + b0.z + ea * w0.z;  v2 = v2 > 0.f ? v2 : 0.2f * v2;
    float v3 = a0.w + b0.w + ea * w0.w;  v3 = v3 > 0.f ? v3 : 0.2f * v3;
    float v4 = a1.x + b1.x + ea * w1.x;  v4 = v4 > 0.f ? v4 : 0.2f * v4;
    float v5 = a1.y + b1.y + ea * w1.y;  v5 = v5 > 0.f ? v5 : 0.2f * v5;
    float v6 = a1.z + b1.z + ea * w1.z;  v6 = v6 > 0.f ? v6 : 0.2f * v6;
    float v7 = a1.w + b1.w + ea * w1.w;  v7 = v7 > 0.f ? v7 : 0.2f * v7;

    float lg = v0 * at0.x + v1 * at0.y + v2 * at0.z + v3 * at0.w
             + v4 * at1.x + v5 * at1.y + v6 * at1.z + v7 * at1.w;
    lg += __shfl_xor_sync(0xffffffffu, lg, 4);
    lg += __shfl_xor_sync(0xffffffffu, lg, 2);
    lg += __shfl_xor_sync(0xffffffffu, lg, 1);

    if (!valid) return;
    float p = __expf(lg);
    if (cg == 0) atomicAdd(&g_denom[d], p);

    float* ptr = &g_accum[(size_t)d * 64 + cg * 8];
    asm volatile("red.global.add.v4.f32 [%0], {%1, %2, %3, %4};"
                 :: "l"(ptr), "f"(a0.x * p), "f"(a0.y * p), "f"(a0.z * p), "f"(a0.w * p)
                 : "memory");
    asm volatile("red.global.add.v4.f32 [%0], {%1, %2, %3, %4};"
                 :: "l"(ptr + 4), "f"(a1.x * p), "f"(a1.y * p), "f"(a1.z * p), "f"(a1.w * p)
                 : "memory");
}

// ---------------- final node pass: h2 = ELU(accum/denom + bias), fused mean-pool -----
__global__ void k_nodefin_pool(const float* __restrict__ bias, const int* __restrict__ batch) {
    int i = blockIdx.x * blockDim.x + threadIdx.x;
    if (i >= NN * 16) return;
    int n = i >> 4, cg = i & 15;

    float4 a = *(float4*)&g_accum[(size_t)n * 64 + cg * 4];
    float inv = 1.f / (g_denom[n] + 1e-16f);
    float4 b = __ldg((const float4*)&bias[cg * 4]);
    float x0 = a.x * inv + b.x;  x0 = x0 > 0.f ? x0 : expm1f(x0);
    float x1 = a.y * inv + b.y;  x1 = x1 > 0.f ? x1 : expm1f(x1);
    float x2 = a.z * inv + b.z;  x2 = x2 > 0.f ? x2 : expm1f(x2);
    float x3 = a.w * inv + b.w;  x3 = x3 > 0.f ? x3 : expm1f(x3);

    int g = batch[n];
    float* ptr = &g_gsum[g * 64 + cg * 4];
    asm volatile("red.global.add.v4.f32 [%0], {%1, %2, %3, %4};"
                 :: "l"(ptr), "f"(x0), "f"(x1), "f"(x2), "f"(x3)
                 : "memory");
    if (cg == 0) atomicAdd(&g_gcnt[g], 1.f);
}

// ---------------- head: relu(fc1) -> BN(eval) -> fc3 ----------------
__global__ void k_head(const float* __restrict__ Wfc1, const float* __restrict__ bfc1,
                       const float* __restrict__ gamma, const float* __restrict__ beta,
                       const float* __restrict__ mean, const float* __restrict__ var,
                       const float* __restrict__ Wfc3, const float* __restrict__ bfc3,
                       float* __restrict__ out) {
    int g = threadIdx.x;
    if (g >= GG) return;
    float cnt = fmaxf(g_gcnt[g], 1.f);
    float pooled[64];
#pragma unroll
    for (int c = 0; c < 64; c++) pooled[c] = g_gsum[g * 64 + c] / cnt;
    float acc = bfc3[0];
    for (int j = 0; j < 32; j++) {
        float z = bfc1[j];
#pragma unroll
        for (int c = 0; c < 64; c++) z = fmaf(pooled[c], Wfc1[c * 32 + j], z);
        z = fmaxf(z, 0.f);
        z = (z - mean[j]) * rsqrtf(var[j] + 1e-5f) * gamma[j] + beta[j];
        acc = fmaf(z, Wfc3[j], acc);
    }
    out[g] = acc;
}

// ---------------- launch ----------------
extern "C" void kernel_launch(void* const* d_in, const int* in_sizes, int n_in,
                              void* d_out, int out_size) {
    const float* x      = (const float*)d_in[0];
    const int*   eidx   = (const int*)d_in[1];
    const float* eattr  = (const float*)d_in[2];
    const int*   batch  = (const int*)d_in[3];
    const float* Wl1 = (const float*)d_in[4];   const float* bl1 = (const float*)d_in[5];
    const float* Wr1 = (const float*)d_in[6];   const float* br1 = (const float*)d_in[7];
    const float* We1 = (const float*)d_in[8];   const float* att1 = (const float*)d_in[9];
    const float* bias1 = (const float*)d_in[10];
    const float* Wl2 = (const float*)d_in[11];  const float* bl2 = (const float*)d_in[12];
    const float* Wr2 = (const float*)d_in[13];  const float* br2 = (const float*)d_in[14];
    const float* We2 = (const float*)d_in[15];  const float* att2 = (const float*)d_in[16];
    const float* bias2 = (const float*)d_in[17];
    const float* Wfc1 = (const float*)d_in[18]; const float* bfc1 = (const float*)d_in[19];
    const float* gamma = (const float*)d_in[20]; const float* beta = (const float*)d_in[21];
    const float* mean = (const float*)d_in[22];  const float* var = (const float*)d_in[23];
    const float* Wfc3 = (const float*)d_in[24];  const float* bfc3 = (const float*)d_in[25];
    float* out = (float*)d_out;

    const int* e_src = eidx;        // edge_index[0]
    const int* e_dst = eidx + EE;   // edge_index[1]

    const int TB = 256;
    const int nBlocksN    = (NN + TB - 1) / TB;
    const int nBlocksE    = (EE + TB - 1) / TB;
    const int nBlocksEdge = (ETOT + 31) / 32;           // 32 edges per block
    const int nBlocksN16  = (NN * 16 + TB - 1) / TB;
    const int nBlocksGemm = (NN + 63) / 64;

    const int smem1 = (2 * 128 * 64 + 64 * 128) * 4;    // 96 KB
    const int smem2 = (2 * 64 * 64 + 64 * 64) * 4;      // 48 KB
    cudaFuncSetAttribute(k_gemm2<128, 0>, cudaFuncAttributeMaxDynamicSharedMemorySize, smem1);
    cudaFuncSetAttribute(k_gemm2<64, 1>,  cudaFuncAttributeMaxDynamicSharedMemorySize, smem2);

    // self-loop mean attr
    k_init0<<<nBlocksN, TB>>>();
    k_loopsum<<<nBlocksE, TB>>>(e_dst, eattr);
    k_loopattr<<<nBlocksN, TB>>>();

    // ---- layer 1 (gemm also zeroes accum/denom) ----
    k_gemm2<128, 0><<<nBlocksGemm, TB, smem1>>>(x, Wl1, bl1, Wr1, br1, nullptr);
    k_edge<<<nBlocksEdge, TB>>>(e_src, e_dst, eattr, We1, att1);

    // ---- layer 2 (ELU of layer-1 fused into GEMM load; epilogue re-zeroes accum) ----
    k_gemm2<64, 1><<<nBlocksGemm, TB, smem2>>>(nullptr, Wl2, bl2, Wr2, br2, bias1);
    k_edge<<<nBlocksEdge, TB>>>(e_src, e_dst, eattr, We2, att2);

    // ---- finish layer 2 + pool + head ----
    k_nodefin_pool<<<nBlocksN16, TB>>>(bias2, batch);
    k_head<<<1, 64>>>(Wfc1, bfc1, gamma, beta, mean, var, Wfc3, bfc3, out);
}

// round 4
// speedup vs baseline: 1.3246x; 1.3246x over previous
#include <cuda_runtime.h>
#include <math.h>

#define NN 50000
#define EE 1600000
#define GG 64
#define ETOT (EE + NN)   // 1650000, divisible by 16

typedef unsigned long long u64;

// ---------------- device scratch ----------------
__device__ __align__(16) float g_loop_s[NN];
__device__ __align__(16) float g_loop_c[NN];
__device__ __align__(16) float g_loop_attr[NN];
__device__ __align__(16) float g_xl[NN * 64];
__device__ __align__(16) float g_xr[NN * 64];
__device__ __align__(16) float g_accum[NN * 64];
__device__ __align__(16) float g_denom[NN];
__device__ __align__(16) float g_gsum[GG * 64];
__device__ float          g_gcnt[GG];

// ---------------- f32x2 helpers (FFMA2 path, PTX-only) ----------------
__device__ __forceinline__ u64 ffma2(u64 a, u64 b, u64 c) {
    u64 d;
    asm("fma.rn.f32x2 %0, %1, %2, %3;" : "=l"(d) : "l"(a), "l"(b), "l"(c));
    return d;
}
__device__ __forceinline__ u64 pack2(float x) {
    u64 d;
    asm("mov.b64 %0, {%1, %1};" : "=l"(d) : "f"(x));
    return d;
}
__device__ __forceinline__ void unpack2(u64 v, float& lo, float& hi) {
    asm("mov.b64 {%0, %1}, %2;" : "=f"(lo), "=f"(hi) : "l"(v));
}

// ---------------- init ----------------
__global__ void k_init0() {
    int i = blockIdx.x * blockDim.x + threadIdx.x;
    if (i < NN) { g_loop_s[i] = 0.f; g_loop_c[i] = 0.f; }
    if (i < GG * 64) g_gsum[i] = 0.f;
    if (i < GG) g_gcnt[i] = 0.f;
}

// ---------------- self-loop attr (fill_value='mean') ----------------
__global__ void k_loopsum(const int* __restrict__ dst, const float* __restrict__ ea) {
    int e = blockIdx.x * blockDim.x + threadIdx.x;
    if (e >= EE) return;
    int d = dst[e];
    atomicAdd(&g_loop_s[d], ea[e]);
    atomicAdd(&g_loop_c[d], 1.f);
}

__global__ void k_loopattr() {
    int n = blockIdx.x * blockDim.x + threadIdx.x;
    if (n >= NN) return;
    g_loop_attr[n] = g_loop_s[n] / fmaxf(g_loop_c[n], 1.f);
}

// ---------------- fused dual GEMM: xl = f(X)@Wl+bl, xr = f(X)@Wr+br --------------
// 256 threads, 64 nodes/block. X tile AND both weight matrices staged in SMEM.
// Inner loop uses packed fma.rn.f32x2 (FFMA2): channel pairs in 64-bit accumulators.
// FUSE_ELU: reconstruct h = ELU(accum/denom + ebias) instead of reading Xg.
// Epilogue also zeroes g_accum/g_denom for this block's rows (next layer's scatter).
template <int K, int FUSE_ELU>
__global__ __launch_bounds__(256) void k_gemm2(
        const float* __restrict__ Xg,
        const float* __restrict__ Wl, const float* __restrict__ bl,
        const float* __restrict__ Wr, const float* __restrict__ br,
        const float* __restrict__ ebias) {
    extern __shared__ float sh[];
    float* Wls = sh;                 // K*64
    float* Wrs = sh + K * 64;        // K*64
    float* Xs  = sh + 2 * K * 64;    // 64*K

    int t = threadIdx.x;
    int base = blockIdx.x * 64;

    // stage weights (coalesced float4)
    for (int i = t; i < K * 16; i += 256) {
        *(float4*)&Wls[i * 4] = __ldg((const float4*)&Wl[i * 4]);
        *(float4*)&Wrs[i * 4] = __ldg((const float4*)&Wr[i * 4]);
    }
    // stage X tile
    const int K4 = K / 4;
    for (int i = t; i < 64 * K4; i += 256) {
        int row = i / K4, c4 = i - row * K4;
        int node = base + row;
        float4 v = make_float4(0.f, 0.f, 0.f, 0.f);
        if (node < NN) {
            if (FUSE_ELU) {
                float4 a = *(const float4*)&g_accum[(size_t)node * 64 + c4 * 4];
                float inv = 1.f / (g_denom[node] + 1e-16f);
                float4 b = __ldg((const float4*)&ebias[c4 * 4]);
                v.x = a.x * inv + b.x;  v.x = v.x > 0.f ? v.x : expm1f(v.x);
                v.y = a.y * inv + b.y;  v.y = v.y > 0.f ? v.y : expm1f(v.y);
                v.z = a.z * inv + b.z;  v.z = v.z > 0.f ? v.z : expm1f(v.z);
                v.w = a.w * inv + b.w;  v.w = v.w > 0.f ? v.w : expm1f(v.w);
            } else {
                v = __ldg((const float4*)&Xg[(size_t)node * K + c4 * 4]);
            }
        }
        *(float4*)&Xs[row * K + c4 * 4] = v;
    }
    __syncthreads();

    int cg = t & 15;            // 4 output channels: [cg*4, cg*4+4)
    int ng = t >> 4;            // 4 nodes
    int nb = base + ng * 4;

    // bias pairs
    u64 bl0 = *(const u64*)&bl[cg * 4];
    u64 bl1 = *(const u64*)&bl[cg * 4 + 2];
    u64 br0 = *(const u64*)&br[cg * 4];
    u64 br1 = *(const u64*)&br[cg * 4 + 2];

    u64 accL[4][2], accR[4][2];
#pragma unroll
    for (int n = 0; n < 4; n++) {
        accL[n][0] = bl0; accL[n][1] = bl1;
        accR[n][0] = br0; accR[n][1] = br1;
    }

    const float* xs0 = &Xs[(ng * 4 + 0) * K];
    const float* xs1 = &Xs[(ng * 4 + 1) * K];
    const float* xs2 = &Xs[(ng * 4 + 2) * K];
    const float* xs3 = &Xs[(ng * 4 + 3) * K];

#pragma unroll 4
    for (int k = 0; k < K; k++) {
        ulonglong2 wl = *(const ulonglong2*)&Wls[k * 64 + cg * 4];
        ulonglong2 wr = *(const ulonglong2*)&Wrs[k * 64 + cg * 4];
        u64 x0 = pack2(xs0[k]);
        u64 x1 = pack2(xs1[k]);
        u64 x2 = pack2(xs2[k]);
        u64 x3 = pack2(xs3[k]);
        accL[0][0] = ffma2(x0, wl.x, accL[0][0]);  accL[0][1] = ffma2(x0, wl.y, accL[0][1]);
        accR[0][0] = ffma2(x0, wr.x, accR[0][0]);  accR[0][1] = ffma2(x0, wr.y, accR[0][1]);
        accL[1][0] = ffma2(x1, wl.x, accL[1][0]);  accL[1][1] = ffma2(x1, wl.y, accL[1][1]);
        accR[1][0] = ffma2(x1, wr.x, accR[1][0]);  accR[1][1] = ffma2(x1, wr.y, accR[1][1]);
        accL[2][0] = ffma2(x2, wl.x, accL[2][0]);  accL[2][1] = ffma2(x2, wl.y, accL[2][1]);
        accR[2][0] = ffma2(x2, wr.x, accR[2][0]);  accR[2][1] = ffma2(x2, wr.y, accR[2][1]);
        accL[3][0] = ffma2(x3, wl.x, accL[3][0]);  accL[3][1] = ffma2(x3, wl.y, accL[3][1]);
        accR[3][0] = ffma2(x3, wr.x, accR[3][0]);  accR[3][1] = ffma2(x3, wr.y, accR[3][1]);
    }

    const float4 z4 = make_float4(0.f, 0.f, 0.f, 0.f);
#pragma unroll
    for (int n = 0; n < 4; n++) {
        if (nb + n < NN) {
            float4 L, R;
            unpack2(accL[n][0], L.x, L.y);  unpack2(accL[n][1], L.z, L.w);
            unpack2(accR[n][0], R.x, R.y);  unpack2(accR[n][1], R.z, R.w);
            *(float4*)&g_xl[(size_t)(nb + n) * 64 + cg * 4] = L;
            *(float4*)&g_xr[(size_t)(nb + n) * 64 + cg * 4] = R;
            *(float4*)&g_accum[(size_t)(nb + n) * 64 + cg * 4] = z4;
        }
    }
    if (t < 64 && base + t < NN) g_denom[base + t] = 0.f;
}

// ---------------- fused edge pass (softmax shift-invariant: no segment-max) ----------
// 16 threads/edge (dense 256B gathers): gather xl[src], xr[dst]; leakyrelu; logit;
// p = exp(logit); scatter p*xl[src] to accum[dst] and p to denom[dst].
__global__ __launch_bounds__(256) void k_edge(
        const int* __restrict__ src, const int* __restrict__ dst,
        const float* __restrict__ eattr,
        const float* __restrict__ We, const float* __restrict__ att) {
    int t = threadIdx.x;
    int e = blockIdx.x * 16 + (t >> 4);
    int cg = t & 15;
    if (e >= ETOT) return;   // exact grid (ETOT % 16 == 0)

    int s, d; float ea;
    if (e < EE) { s = src[e]; d = dst[e]; ea = eattr[e]; }
    else        { s = d = e - EE; ea = g_loop_attr[e - EE]; }

    float4 a  = *(const float4*)&g_xl[(size_t)s * 64 + cg * 4];
    float4 b  = *(const float4*)&g_xr[(size_t)d * 64 + cg * 4];
    float4 w  = __ldg((const float4*)&We[cg * 4]);
    float4 at = __ldg((const float4*)&att[cg * 4]);

    float vx = a.x + b.x + ea * w.x;  vx = vx > 0.f ? vx : 0.2f * vx;
    float vy = a.y + b.y + ea * w.y;  vy = vy > 0.f ? vy : 0.2f * vy;
    float vz = a.z + b.z + ea * w.z;  vz = vz > 0.f ? vz : 0.2f * vz;
    float vw = a.w + b.w + ea * w.w;  vw = vw > 0.f ? vw : 0.2f * vw;

    float lg = vx * at.x + vy * at.y + vz * at.z + vw * at.w;
    lg += __shfl_xor_sync(0xffffffffu, lg, 8);
    lg += __shfl_xor_sync(0xffffffffu, lg, 4);
    lg += __shfl_xor_sync(0xffffffffu, lg, 2);
    lg += __shfl_xor_sync(0xffffffffu, lg, 1);

    float p = __expf(lg);
    if (cg == 0) atomicAdd(&g_denom[d], p);

    float* ptr = &g_accum[(size_t)d * 64 + cg * 4];
    asm volatile("red.global.add.v4.f32 [%0], {%1, %2, %3, %4};"
                 :: "l"(ptr), "f"(a.x * p), "f"(a.y * p), "f"(a.z * p), "f"(a.w * p)
                 : "memory");
}

// ---------------- final node pass: h2 = ELU(accum/denom + bias), fused mean-pool -----
__global__ void k_nodefin_pool(const float* __restrict__ bias, const int* __restrict__ batch) {
    int i = blockIdx.x * blockDim.x + threadIdx.x;
    if (i >= NN * 16) return;
    int n = i >> 4, cg = i & 15;

    float4 a = *(float4*)&g_accum[(size_t)n * 64 + cg * 4];
    float inv = 1.f / (g_denom[n] + 1e-16f);
    float4 b = __ldg((const float4*)&bias[cg * 4]);
    float x0 = a.x * inv + b.x;  x0 = x0 > 0.f ? x0 : expm1f(x0);
    float x1 = a.y * inv + b.y;  x1 = x1 > 0.f ? x1 : expm1f(x1);
    float x2 = a.z * inv + b.z;  x2 = x2 > 0.f ? x2 : expm1f(x2);
    float x3 = a.w * inv + b.w;  x3 = x3 > 0.f ? x3 : expm1f(x3);

    int g = batch[n];
    float* ptr = &g_gsum[g * 64 + cg * 4];
    asm volatile("red.global.add.v4.f32 [%0], {%1, %2, %3, %4};"
                 :: "l"(ptr), "f"(x0), "f"(x1), "f"(x2), "f"(x3)
                 : "memory");
    if (cg == 0) atomicAdd(&g_gcnt[g], 1.f);
}

// ---------------- head: relu(fc1) -> BN(eval) -> fc3 ----------------
__global__ void k_head(const float* __restrict__ Wfc1, const float* __restrict__ bfc1,
                       const float* __restrict__ gamma, const float* __restrict__ beta,
                       const float* __restrict__ mean, const float* __restrict__ var,
                       const float* __restrict__ Wfc3, const float* __restrict__ bfc3,
                       float* __restrict__ out) {
    int g = threadIdx.x;
    if (g >= GG) return;
    float cnt = fmaxf(g_gcnt[g], 1.f);
    float pooled[64];
#pragma unroll
    for (int c = 0; c < 64; c++) pooled[c] = g_gsum[g * 64 + c] / cnt;
    float acc = bfc3[0];
    for (int j = 0; j < 32; j++) {
        float z = bfc1[j];
#pragma unroll
        for (int c = 0; c < 64; c++) z = fmaf(pooled[c], Wfc1[c * 32 + j], z);
        z = fmaxf(z, 0.f);
        z = (z - mean[j]) * rsqrtf(var[j] + 1e-5f) * gamma[j] + beta[j];
        acc = fmaf(z, Wfc3[j], acc);
    }
    out[g] = acc;
}

// ---------------- launch ----------------
extern "C" void kernel_launch(void* const* d_in, const int* in_sizes, int n_in,
                              void* d_out, int out_size) {
    const float* x      = (const float*)d_in[0];
    const int*   eidx   = (const int*)d_in[1];
    const float* eattr  = (const float*)d_in[2];
    const int*   batch  = (const int*)d_in[3];
    const float* Wl1 = (const float*)d_in[4];   const float* bl1 = (const float*)d_in[5];
    const float* Wr1 = (const float*)d_in[6];   const float* br1 = (const float*)d_in[7];
    const float* We1 = (const float*)d_in[8];   const float* att1 = (const float*)d_in[9];
    const float* bias1 = (const float*)d_in[10];
    const float* Wl2 = (const float*)d_in[11];  const float* bl2 = (const float*)d_in[12];
    const float* Wr2 = (const float*)d_in[13];  const float* br2 = (const float*)d_in[14];
    const float* We2 = (const float*)d_in[15];  const float* att2 = (const float*)d_in[16];
    const float* bias2 = (const float*)d_in[17];
    const float* Wfc1 = (const float*)d_in[18]; const float* bfc1 = (const float*)d_in[19];
    const float* gamma = (const float*)d_in[20]; const float* beta = (const float*)d_in[21];
    const float* mean = (const float*)d_in[22];  const float* var = (const float*)d_in[23];
    const float* Wfc3 = (const float*)d_in[24];  const float* bfc3 = (const float*)d_in[25];
    float* out = (float*)d_out;

    const int* e_src = eidx;        // edge_index[0]
    const int* e_dst = eidx + EE;   // edge_index[1]

    const int TB = 256;
    const int nBlocksN    = (NN + TB - 1) / TB;
    const int nBlocksE    = (EE + TB - 1) / TB;
    const int nBlocksEdge = ETOT / 16;                  // 16 edges per block
    const int nBlocksN16  = (NN * 16 + TB - 1) / TB;
    const int nBlocksGemm = (NN + 63) / 64;

    const int smem1 = (2 * 128 * 64 + 64 * 128) * 4;    // 96 KB
    const int smem2 = (2 * 64 * 64 + 64 * 64) * 4;      // 48 KB
    cudaFuncSetAttribute(k_gemm2<128, 0>, cudaFuncAttributeMaxDynamicSharedMemorySize, smem1);
    cudaFuncSetAttribute(k_gemm2<64, 1>,  cudaFuncAttributeMaxDynamicSharedMemorySize, smem2);

    // self-loop mean attr
    k_init0<<<nBlocksN, TB>>>();
    k_loopsum<<<nBlocksE, TB>>>(e_dst, eattr);
    k_loopattr<<<nBlocksN, TB>>>();

    // ---- layer 1 (gemm also zeroes accum/denom) ----
    k_gemm2<128, 0><<<nBlocksGemm, TB, smem1>>>(x, Wl1, bl1, Wr1, br1, nullptr);
    k_edge<<<nBlocksEdge, TB>>>(e_src, e_dst, eattr, We1, att1);

    // ---- layer 2 (ELU of layer-1 fused into GEMM load; epilogue re-zeroes accum) ----
    k_gemm2<64, 1><<<nBlocksGemm, TB, smem2>>>(nullptr, Wl2, bl2, Wr2, br2, bias1);
    k_edge<<<nBlocksEdge, TB>>>(e_src, e_dst, eattr, We2, att2);

    // ---- finish layer 2 + pool + head ----
    k_nodefin_pool<<<nBlocksN16, TB>>>(bias2, batch);
    k_head<<<1, 64>>>(Wfc1, bfc1, gamma, beta, mean, var, Wfc3, bfc3, out);
}

// round 5
// speedup vs baseline: 1.7599x; 1.3286x over previous
#include <cuda_runtime.h>
#include <math.h>

#define NN 50000
#define EE 1600000
#define GG 64
#define NB 98            // (NN+511)/512 scan blocks

typedef unsigned long long u64;

// ---------------- device scratch ----------------
__device__ __align__(16) float g_xl[NN * 64];
__device__ __align__(16) float g_xr[NN * 64];
__device__ __align__(16) float g_h1[NN * 64];
__device__ __align__(16) float g_gsum[GG * 64];
__device__ float g_gcnt[GG];
__device__ int   g_cnt[NN];
__device__ int   g_off[NN];
__device__ int   g_cursor[NN];
__device__ int   g_bsum[128];
__device__ int   g_ssrc[EE];
__device__ float g_sea[EE];

// ---------------- f32x2 helpers (FFMA2, PTX-only) ----------------
__device__ __forceinline__ u64 ffma2(u64 a, u64 b, u64 c) {
    u64 d;
    asm("fma.rn.f32x2 %0, %1, %2, %3;" : "=l"(d) : "l"(a), "l"(b), "l"(c));
    return d;
}
__device__ __forceinline__ u64 pack2(float x) {
    u64 d;
    asm("mov.b64 %0, {%1, %1};" : "=l"(d) : "f"(x));
    return d;
}
__device__ __forceinline__ void unpack2(u64 v, float& lo, float& hi) {
    asm("mov.b64 {%0, %1}, %2;" : "=f"(lo), "=f"(hi) : "l"(v));
}

// ---------------- init: zero counters ----------------
__global__ void k_init0() {
    int i = blockIdx.x * blockDim.x + threadIdx.x;
    if (i < NN) g_cnt[i] = 0;
    if (i < GG * 64) g_gsum[i] = 0.f;
    if (i < GG) g_gcnt[i] = 0.f;
}

// ---------------- CSR build: histogram, scan, scatter ----------------
__global__ void k_hist(const int* __restrict__ dst) {
    int e = blockIdx.x * blockDim.x + threadIdx.x;
    if (e >= EE) return;
    atomicAdd(&g_cnt[dst[e]], 1);
}

__global__ void k_scan1() {            // 512 threads/block, NB blocks
    __shared__ int wsum[16];
    int i = blockIdx.x * 512 + threadIdx.x;
    int lane = threadIdx.x & 31, wid = threadIdx.x >> 5;
    int v = (i < NN) ? g_cnt[i] : 0;
    int x = v;
#pragma unroll
    for (int o = 1; o < 32; o <<= 1) {
        int y = __shfl_up_sync(0xffffffffu, x, o);
        if (lane >= o) x += y;
    }
    if (lane == 31) wsum[wid] = x;
    __syncthreads();
    if (wid == 0) {
        int s = (lane < 16) ? wsum[lane] : 0;
#pragma unroll
        for (int o = 1; o < 16; o <<= 1) {
            int y = __shfl_up_sync(0xffffffffu, s, o);
            if (lane >= o) s += y;
        }
        if (lane < 16) wsum[lane] = s;
    }
    __syncthreads();
    int prefix = (wid > 0) ? wsum[wid - 1] : 0;
    if (i < NN) g_off[i] = prefix + x - v;        // exclusive within block
    if (threadIdx.x == 511) g_bsum[blockIdx.x] = prefix + x;  // block total
}

__global__ void k_scan2() {            // 1 block, 128 threads
    __shared__ int sh[128];
    int t = threadIdx.x;
    int v = (t < NB) ? g_bsum[t] : 0;
    sh[t] = v;
    __syncthreads();
    for (int o = 1; o < 128; o <<= 1) {
        int y = (t >= o) ? sh[t - o] : 0;
        __syncthreads();
        sh[t] += y;
        __syncthreads();
    }
    if (t < NB) g_bsum[t] = sh[t] - v;            // exclusive
}

__global__ void k_scan3() {
    int i = blockIdx.x * blockDim.x + threadIdx.x;
    if (i >= NN) return;
    int o = g_off[i] + g_bsum[i >> 9];
    g_off[i] = o;
    g_cursor[i] = o;
}

__global__ void k_escatter(const int* __restrict__ src, const int* __restrict__ dst,
                           const float* __restrict__ ea) {
    int e = blockIdx.x * blockDim.x + threadIdx.x;
    if (e >= EE) return;
    int d = dst[e];
    int pos = atomicAdd(&g_cursor[d], 1);
    g_ssrc[pos] = src[e];
    g_sea[pos] = ea[e];
}

// ---------------- fused dual GEMM: xl = X@Wl+bl, xr = X@Wr+br --------------
// 256 threads, 64 nodes/block. X tile + both weight matrices in SMEM; FFMA2 inner loop.
// USE_H1: read from g_h1 (layer-2 input) instead of Xg.
template <int K, int USE_H1>
__global__ __launch_bounds__(256) void k_gemm2(
        const float* __restrict__ Xg,
        const float* __restrict__ Wl, const float* __restrict__ bl,
        const float* __restrict__ Wr, const float* __restrict__ br) {
    extern __shared__ float sh[];
    float* Wls = sh;                 // K*64
    float* Wrs = sh + K * 64;        // K*64
    float* Xs  = sh + 2 * K * 64;    // 64*K

    int t = threadIdx.x;
    int base = blockIdx.x * 64;
    const float* __restrict__ X = USE_H1 ? g_h1 : Xg;

    for (int i = t; i < K * 16; i += 256) {
        *(float4*)&Wls[i * 4] = __ldg((const float4*)&Wl[i * 4]);
        *(float4*)&Wrs[i * 4] = __ldg((const float4*)&Wr[i * 4]);
    }
    const int K4 = K / 4;
    for (int i = t; i < 64 * K4; i += 256) {
        int row = i / K4, c4 = i - row * K4;
        int node = base + row;
        float4 v = make_float4(0.f, 0.f, 0.f, 0.f);
        if (node < NN) v = __ldg((const float4*)&X[(size_t)node * K + c4 * 4]);
        *(float4*)&Xs[row * K + c4 * 4] = v;
    }
    __syncthreads();

    int cg = t & 15;            // 4 output channels
    int ng = t >> 4;            // 4 nodes
    int nb = base + ng * 4;

    u64 bl0 = *(const u64*)&bl[cg * 4];
    u64 bl1 = *(const u64*)&bl[cg * 4 + 2];
    u64 br0 = *(const u64*)&br[cg * 4];
    u64 br1 = *(const u64*)&br[cg * 4 + 2];

    u64 accL[4][2], accR[4][2];
#pragma unroll
    for (int n = 0; n < 4; n++) {
        accL[n][0] = bl0; accL[n][1] = bl1;
        accR[n][0] = br0; accR[n][1] = br1;
    }

    const float* xs0 = &Xs[(ng * 4 + 0) * K];
    const float* xs1 = &Xs[(ng * 4 + 1) * K];
    const float* xs2 = &Xs[(ng * 4 + 2) * K];
    const float* xs3 = &Xs[(ng * 4 + 3) * K];

#pragma unroll 4
    for (int k = 0; k < K; k++) {
        ulonglong2 wl = *(const ulonglong2*)&Wls[k * 64 + cg * 4];
        ulonglong2 wr = *(const ulonglong2*)&Wrs[k * 64 + cg * 4];
        u64 x0 = pack2(xs0[k]);
        u64 x1 = pack2(xs1[k]);
        u64 x2 = pack2(xs2[k]);
        u64 x3 = pack2(xs3[k]);
        accL[0][0] = ffma2(x0, wl.x, accL[0][0]);  accL[0][1] = ffma2(x0, wl.y, accL[0][1]);
        accR[0][0] = ffma2(x0, wr.x, accR[0][0]);  accR[0][1] = ffma2(x0, wr.y, accR[0][1]);
        accL[1][0] = ffma2(x1, wl.x, accL[1][0]);  accL[1][1] = ffma2(x1, wl.y, accL[1][1]);
        accR[1][0] = ffma2(x1, wr.x, accR[1][0]);  accR[1][1] = ffma2(x1, wr.y, accR[1][1]);
        accL[2][0] = ffma2(x2, wl.x, accL[2][0]);  accL[2][1] = ffma2(x2, wl.y, accL[2][1]);
        accR[2][0] = ffma2(x2, wr.x, accR[2][0]);  accR[2][1] = ffma2(x2, wr.y, accR[2][1]);
        accL[3][0] = ffma2(x3, wl.x, accL[3][0]);  accL[3][1] = ffma2(x3, wl.y, accL[3][1]);
        accR[3][0] = ffma2(x3, wr.x, accR[3][0]);  accR[3][1] = ffma2(x3, wr.y, accR[3][1]);
    }

#pragma unroll
    for (int n = 0; n < 4; n++) {
        if (nb + n < NN) {
            float4 L, R;
            unpack2(accL[n][0], L.x, L.y);  unpack2(accL[n][1], L.z, L.w);
            unpack2(accR[n][0], R.x, R.y);  unpack2(accR[n][1], R.z, R.w);
            *(float4*)&g_xl[(size_t)(nb + n) * 64 + cg * 4] = L;
            *(float4*)&g_xr[(size_t)(nb + n) * 64 + cg * 4] = R;
        }
    }
}

// ---------------- warp-per-dst edge pass over CSR ----------------
// 16 threads/edge, 2 edges in flight per warp. Softmax finished in registers;
// self-loop (mean edge attr) handled inline. LAYER==0 writes h1; LAYER==1 pools.
template <int LAYER>
__global__ __launch_bounds__(256) void k_edge_sorted(
        const float* __restrict__ We, const float* __restrict__ att,
        const float* __restrict__ bias, const int* __restrict__ batch) {
    int gw = (blockIdx.x * 256 + threadIdx.x) >> 5;
    if (gw >= NN) return;
    int lane = threadIdx.x & 31;
    int half = lane >> 4, cg = lane & 15;
    unsigned m16 = 0xFFFFu << (half * 16);

    int d = gw;
    int off = g_off[d], cnt = g_cnt[d];
    int end = off + cnt;

    float4 b  = *(const float4*)&g_xr[(size_t)d * 64 + cg * 4];
    float4 w4 = __ldg((const float4*)&We[cg * 4]);
    float4 at = __ldg((const float4*)&att[cg * 4]);

    float4 acc = make_float4(0.f, 0.f, 0.f, 0.f);
    float den = 0.f, easum = 0.f;

    for (int i = off + half; i < end; i += 2) {
        int s = g_ssrc[i];
        float ea = g_sea[i];
        easum += ea;
        float4 a = *(const float4*)&g_xl[(size_t)s * 64 + cg * 4];
        float vx = a.x + b.x + ea * w4.x;  vx = vx > 0.f ? vx : 0.2f * vx;
        float vy = a.y + b.y + ea * w4.y;  vy = vy > 0.f ? vy : 0.2f * vy;
        float vz = a.z + b.z + ea * w4.z;  vz = vz > 0.f ? vz : 0.2f * vz;
        float vw = a.w + b.w + ea * w4.w;  vw = vw > 0.f ? vw : 0.2f * vw;
        float lg = vx * at.x + vy * at.y + vz * at.z + vw * at.w;
        lg += __shfl_xor_sync(m16, lg, 8);
        lg += __shfl_xor_sync(m16, lg, 4);
        lg += __shfl_xor_sync(m16, lg, 2);
        lg += __shfl_xor_sync(m16, lg, 1);
        float p = __expf(lg);
        den += p;
        acc.x += p * a.x; acc.y += p * a.y; acc.z += p * a.z; acc.w += p * a.w;
    }
    __syncwarp();
    // combine the two halves
    acc.x += __shfl_xor_sync(0xffffffffu, acc.x, 16);
    acc.y += __shfl_xor_sync(0xffffffffu, acc.y, 16);
    acc.z += __shfl_xor_sync(0xffffffffu, acc.z, 16);
    acc.w += __shfl_xor_sync(0xffffffffu, acc.w, 16);
    den   += __shfl_xor_sync(0xffffffffu, den, 16);
    easum += __shfl_xor_sync(0xffffffffu, easum, 16);

    // self-loop edge: src = dst, ea = mean of incoming edge attrs
    {
        float lea = easum / fmaxf((float)cnt, 1.f);
        float4 a = *(const float4*)&g_xl[(size_t)d * 64 + cg * 4];
        float vx = a.x + b.x + lea * w4.x;  vx = vx > 0.f ? vx : 0.2f * vx;
        float vy = a.y + b.y + lea * w4.y;  vy = vy > 0.f ? vy : 0.2f * vy;
        float vz = a.z + b.z + lea * w4.z;  vz = vz > 0.f ? vz : 0.2f * vz;
        float vw = a.w + b.w + lea * w4.w;  vw = vw > 0.f ? vw : 0.2f * vw;
        float lg = vx * at.x + vy * at.y + vz * at.z + vw * at.w;
        lg += __shfl_xor_sync(0xffffffffu, lg, 8);
        lg += __shfl_xor_sync(0xffffffffu, lg, 4);
        lg += __shfl_xor_sync(0xffffffffu, lg, 2);
        lg += __shfl_xor_sync(0xffffffffu, lg, 1);
        float p = __expf(lg);
        den += p;
        acc.x += p * a.x; acc.y += p * a.y; acc.z += p * a.z; acc.w += p * a.w;
    }

    float inv = 1.f / (den + 1e-16f);
    float4 bias4 = __ldg((const float4*)&bias[cg * 4]);
    float h0 = acc.x * inv + bias4.x;  h0 = h0 > 0.f ? h0 : expm1f(h0);
    float h1 = acc.y * inv + bias4.y;  h1 = h1 > 0.f ? h1 : expm1f(h1);
    float h2 = acc.z * inv + bias4.z;  h2 = h2 > 0.f ? h2 : expm1f(h2);
    float h3 = acc.w * inv + bias4.w;  h3 = h3 > 0.f ? h3 : expm1f(h3);

    if (half == 0) {
        if (LAYER == 0) {
            *(float4*)&g_h1[(size_t)d * 64 + cg * 4] = make_float4(h0, h1, h2, h3);
        } else {
            int g = batch[d];
            float* ptr = &g_gsum[g * 64 + cg * 4];
            asm volatile("red.global.add.v4.f32 [%0], {%1, %2, %3, %4};"
                         :: "l"(ptr), "f"(h0), "f"(h1), "f"(h2), "f"(h3)
                         : "memory");
            if (cg == 0) atomicAdd(&g_gcnt[g], 1.f);
        }
    }
}

// ---------------- head: relu(fc1) -> BN(eval) -> fc3 ----------------
__global__ void k_head(const float* __restrict__ Wfc1, const float* __restrict__ bfc1,
                       const float* __restrict__ gamma, const float* __restrict__ beta,
                       const float* __restrict__ mean, const float* __restrict__ var,
                       const float* __restrict__ Wfc3, const float* __restrict__ bfc3,
                       float* __restrict__ out) {
    int g = threadIdx.x;
    if (g >= GG) return;
    float cnt = fmaxf(g_gcnt[g], 1.f);
    float pooled[64];
#pragma unroll
    for (int c = 0; c < 64; c++) pooled[c] = g_gsum[g * 64 + c] / cnt;
    float acc = bfc3[0];
    for (int j = 0; j < 32; j++) {
        float z = bfc1[j];
#pragma unroll
        for (int c = 0; c < 64; c++) z = fmaf(pooled[c], Wfc1[c * 32 + j], z);
        z = fmaxf(z, 0.f);
        z = (z - mean[j]) * rsqrtf(var[j] + 1e-5f) * gamma[j] + beta[j];
        acc = fmaf(z, Wfc3[j], acc);
    }
    out[g] = acc;
}

// ---------------- launch ----------------
extern "C" void kernel_launch(void* const* d_in, const int* in_sizes, int n_in,
                              void* d_out, int out_size) {
    const float* x      = (const float*)d_in[0];
    const int*   eidx   = (const int*)d_in[1];
    const float* eattr  = (const float*)d_in[2];
    const int*   batch  = (const int*)d_in[3];
    const float* Wl1 = (const float*)d_in[4];   const float* bl1 = (const float*)d_in[5];
    const float* Wr1 = (const float*)d_in[6];   const float* br1 = (const float*)d_in[7];
    const float* We1 = (const float*)d_in[8];   const float* att1 = (const float*)d_in[9];
    const float* bias1 = (const float*)d_in[10];
    const float* Wl2 = (const float*)d_in[11];  const float* bl2 = (const float*)d_in[12];
    const float* Wr2 = (const float*)d_in[13];  const float* br2 = (const float*)d_in[14];
    const float* We2 = (const float*)d_in[15];  const float* att2 = (const float*)d_in[16];
    const float* bias2 = (const float*)d_in[17];
    const float* Wfc1 = (const float*)d_in[18]; const float* bfc1 = (const float*)d_in[19];
    const float* gamma = (const float*)d_in[20]; const float* beta = (const float*)d_in[21];
    const float* mean = (const float*)d_in[22];  const float* var = (const float*)d_in[23];
    const float* Wfc3 = (const float*)d_in[24];  const float* bfc3 = (const float*)d_in[25];
    float* out = (float*)d_out;

    const int* e_src = eidx;        // edge_index[0]
    const int* e_dst = eidx + EE;   // edge_index[1]

    const int TB = 256;
    const int nBlocksN    = (NN + TB - 1) / TB;
    const int nBlocksE    = (EE + TB - 1) / TB;
    const int nBlocksGemm = (NN + 63) / 64;
    const int nBlocksWarp = (NN * 32 + TB - 1) / TB;    // warp per dst

    const int smem1 = (2 * 128 * 64 + 64 * 128) * 4;    // 96 KB
    const int smem2 = (2 * 64 * 64 + 64 * 64) * 4;      // 48 KB
    cudaFuncSetAttribute(k_gemm2<128, 0>, cudaFuncAttributeMaxDynamicSharedMemorySize, smem1);
    cudaFuncSetAttribute(k_gemm2<64, 1>,  cudaFuncAttributeMaxDynamicSharedMemorySize, smem2);

    // ---- CSR build (once; reused by both layers) ----
    k_init0<<<nBlocksN, TB>>>();
    k_hist<<<nBlocksE, TB>>>(e_dst);
    k_scan1<<<NB, 512>>>();
    k_scan2<<<1, 128>>>();
    k_scan3<<<nBlocksN, TB>>>();
    k_escatter<<<nBlocksE, TB>>>(e_src, e_dst, eattr);

    // ---- layer 1 ----
    k_gemm2<128, 0><<<nBlocksGemm, TB, smem1>>>(x, Wl1, bl1, Wr1, br1);
    k_edge_sorted<0><<<nBlocksWarp, TB>>>(We1, att1, bias1, nullptr);   // -> g_h1

    // ---- layer 2 ----
    k_gemm2<64, 1><<<nBlocksGemm, TB, smem2>>>(nullptr, Wl2, bl2, Wr2, br2);
    k_edge_sorted<1><<<nBlocksWarp, TB>>>(We2, att2, bias2, batch);     // -> pool

    // ---- head ----
    k_head<<<1, 64>>>(Wfc1, bfc1, gamma, beta, mean, var, Wfc3, bfc3, out);
}

// round 6
// speedup vs baseline: 1.8469x; 1.0494x over previous
#include <cuda_runtime.h>
#include <cuda_fp16.h>
#include <math.h>

#define NN 50000
#define EE 1600000
#define GG 64
#define NB 98            // (NN+511)/512 scan blocks

typedef unsigned long long u64;

// ---------------- device scratch ----------------
__device__ __align__(16) __half g_xlh[NN * 64];   // fp16 gather table
__device__ __align__(16) float g_xr[NN * 64];
__device__ __align__(16) float g_h1[NN * 64];
__device__ __align__(16) float g_gsum[GG * 64];
__device__ float g_gcnt[GG];
__device__ int   g_cnt[NN];
__device__ int   g_off[NN];
__device__ int   g_cursor[NN];
__device__ int   g_bsum[128];
__device__ __align__(16) int2 g_edges[EE];        // (src, ea-bits) interleaved

// ---------------- f32x2 helpers (FFMA2, PTX-only) ----------------
__device__ __forceinline__ u64 ffma2(u64 a, u64 b, u64 c) {
    u64 d;
    asm("fma.rn.f32x2 %0, %1, %2, %3;" : "=l"(d) : "l"(a), "l"(b), "l"(c));
    return d;
}
__device__ __forceinline__ u64 pack2(float x) {
    u64 d;
    asm("mov.b64 %0, {%1, %1};" : "=l"(d) : "f"(x));
    return d;
}
__device__ __forceinline__ void unpack2(u64 v, float& lo, float& hi) {
    asm("mov.b64 {%0, %1}, %2;" : "=f"(lo), "=f"(hi) : "l"(v));
}

// ---------------- init ----------------
__global__ void k_init0() {
    int i = blockIdx.x * blockDim.x + threadIdx.x;
    if (i < NN) g_cnt[i] = 0;
    if (i < GG * 64) g_gsum[i] = 0.f;
    if (i < GG) g_gcnt[i] = 0.f;
}

// ---------------- CSR build ----------------
__global__ void k_hist(const int* __restrict__ dst) {
    int e = blockIdx.x * blockDim.x + threadIdx.x;
    if (e >= EE) return;
    atomicAdd(&g_cnt[dst[e]], 1);
}

__global__ void k_scan1() {            // 512 threads/block, NB blocks
    __shared__ int wsum[16];
    int i = blockIdx.x * 512 + threadIdx.x;
    int lane = threadIdx.x & 31, wid = threadIdx.x >> 5;
    int v = (i < NN) ? g_cnt[i] : 0;
    int x = v;
#pragma unroll
    for (int o = 1; o < 32; o <<= 1) {
        int y = __shfl_up_sync(0xffffffffu, x, o);
        if (lane >= o) x += y;
    }
    if (lane == 31) wsum[wid] = x;
    __syncthreads();
    if (wid == 0) {
        int s = (lane < 16) ? wsum[lane] : 0;
#pragma unroll
        for (int o = 1; o < 16; o <<= 1) {
            int y = __shfl_up_sync(0xffffffffu, s, o);
            if (lane >= o) s += y;
        }
        if (lane < 16) wsum[lane] = s;
    }
    __syncthreads();
    int prefix = (wid > 0) ? wsum[wid - 1] : 0;
    if (i < NN) g_off[i] = prefix + x - v;        // exclusive within block
    if (threadIdx.x == 511) g_bsum[blockIdx.x] = prefix + x;  // block total
}

__global__ void k_scan3() {            // per-block prefix over block sums, then finalize
    __shared__ int bpref;
    int b = blockIdx.x;
    if (threadIdx.x < 32) {
        int s = 0;
        for (int j = threadIdx.x; j < b; j += 32) s += g_bsum[j];
#pragma unroll
        for (int o = 16; o; o >>= 1) s += __shfl_xor_sync(0xffffffffu, s, o);
        if (threadIdx.x == 0) bpref = s;
    }
    __syncthreads();
    int i = b * 512 + threadIdx.x;
    if (i < NN) {
        int o = g_off[i] + bpref;
        g_off[i] = o;
        g_cursor[i] = o;
    }
}

__global__ void k_escatter(const int* __restrict__ src, const int* __restrict__ dst,
                           const float* __restrict__ ea) {
    int e = blockIdx.x * blockDim.x + threadIdx.x;
    if (e >= EE) return;
    int d = dst[e];
    int pos = atomicAdd(&g_cursor[d], 1);
    g_edges[pos] = make_int2(src[e], __float_as_int(ea[e]));
}

// ---------------- fused dual GEMM: xl = X@Wl+bl (fp16 out), xr = X@Wr+br --------------
// 256 threads, 64 nodes/block. X tile + both weight matrices in SMEM; FFMA2 inner loop.
template <int K, int USE_H1>
__global__ __launch_bounds__(256) void k_gemm2(
        const float* __restrict__ Xg,
        const float* __restrict__ Wl, const float* __restrict__ bl,
        const float* __restrict__ Wr, const float* __restrict__ br) {
    extern __shared__ float sh[];
    float* Wls = sh;                 // K*64
    float* Wrs = sh + K * 64;        // K*64
    float* Xs  = sh + 2 * K * 64;    // 64*K

    int t = threadIdx.x;
    int base = blockIdx.x * 64;
    const float* __restrict__ X = USE_H1 ? g_h1 : Xg;

    for (int i = t; i < K * 16; i += 256) {
        *(float4*)&Wls[i * 4] = __ldg((const float4*)&Wl[i * 4]);
        *(float4*)&Wrs[i * 4] = __ldg((const float4*)&Wr[i * 4]);
    }
    const int K4 = K / 4;
    for (int i = t; i < 64 * K4; i += 256) {
        int row = i / K4, c4 = i - row * K4;
        int node = base + row;
        float4 v = make_float4(0.f, 0.f, 0.f, 0.f);
        if (node < NN) v = __ldg((const float4*)&X[(size_t)node * K + c4 * 4]);
        *(float4*)&Xs[row * K + c4 * 4] = v;
    }
    __syncthreads();

    int cg = t & 15;            // 4 output channels
    int ng = t >> 4;            // 4 nodes
    int nb = base + ng * 4;

    u64 bl0 = *(const u64*)&bl[cg * 4];
    u64 bl1 = *(const u64*)&bl[cg * 4 + 2];
    u64 br0 = *(const u64*)&br[cg * 4];
    u64 br1 = *(const u64*)&br[cg * 4 + 2];

    u64 accL[4][2], accR[4][2];
#pragma unroll
    for (int n = 0; n < 4; n++) {
        accL[n][0] = bl0; accL[n][1] = bl1;
        accR[n][0] = br0; accR[n][1] = br1;
    }

    const float* xs0 = &Xs[(ng * 4 + 0) * K];
    const float* xs1 = &Xs[(ng * 4 + 1) * K];
    const float* xs2 = &Xs[(ng * 4 + 2) * K];
    const float* xs3 = &Xs[(ng * 4 + 3) * K];

#pragma unroll 4
    for (int k = 0; k < K; k++) {
        ulonglong2 wl = *(const ulonglong2*)&Wls[k * 64 + cg * 4];
        ulonglong2 wr = *(const ulonglong2*)&Wrs[k * 64 + cg * 4];
        u64 x0 = pack2(xs0[k]);
        u64 x1 = pack2(xs1[k]);
        u64 x2 = pack2(xs2[k]);
        u64 x3 = pack2(xs3[k]);
        accL[0][0] = ffma2(x0, wl.x, accL[0][0]);  accL[0][1] = ffma2(x0, wl.y, accL[0][1]);
        accR[0][0] = ffma2(x0, wr.x, accR[0][0]);  accR[0][1] = ffma2(x0, wr.y, accR[0][1]);
        accL[1][0] = ffma2(x1, wl.x, accL[1][0]);  accL[1][1] = ffma2(x1, wl.y, accL[1][1]);
        accR[1][0] = ffma2(x1, wr.x, accR[1][0]);  accR[1][1] = ffma2(x1, wr.y, accR[1][1]);
        accL[2][0] = ffma2(x2, wl.x, accL[2][0]);  accL[2][1] = ffma2(x2, wl.y, accL[2][1]);
        accR[2][0] = ffma2(x2, wr.x, accR[2][0]);  accR[2][1] = ffma2(x2, wr.y, accR[2][1]);
        accL[3][0] = ffma2(x3, wl.x, accL[3][0]);  accL[3][1] = ffma2(x3, wl.y, accL[3][1]);
        accR[3][0] = ffma2(x3, wr.x, accR[3][0]);  accR[3][1] = ffma2(x3, wr.y, accR[3][1]);
    }

#pragma unroll
    for (int n = 0; n < 4; n++) {
        if (nb + n < NN) {
            float4 L, R;
            unpack2(accL[n][0], L.x, L.y);  unpack2(accL[n][1], L.z, L.w);
            unpack2(accR[n][0], R.x, R.y);  unpack2(accR[n][1], R.z, R.w);
            __half2 h01 = __floats2half2_rn(L.x, L.y);
            __half2 h23 = __floats2half2_rn(L.z, L.w);
            uint2 hv;
            hv.x = *(unsigned*)&h01;
            hv.y = *(unsigned*)&h23;
            *(uint2*)&g_xlh[(size_t)(nb + n) * 64 + cg * 4] = hv;
            *(float4*)&g_xr[(size_t)(nb + n) * 64 + cg * 4] = R;
        }
    }
}

// ---------------- warp-per-dst edge pass over CSR (fp16 xl gathers) ----------------
template <int LAYER>
__global__ __launch_bounds__(256) void k_edge_sorted(
        const float* __restrict__ We, const float* __restrict__ att,
        const float* __restrict__ bias, const int* __restrict__ batch) {
    int gw = (blockIdx.x * 256 + threadIdx.x) >> 5;
    if (gw >= NN) return;
    int lane = threadIdx.x & 31;
    int half = lane >> 4, cg = lane & 15;
    unsigned m16 = 0xFFFFu << (half * 16);

    int d = gw;
    int off = g_off[d], cnt = g_cnt[d];
    int end = off + cnt;

    float4 b  = *(const float4*)&g_xr[(size_t)d * 64 + cg * 4];
    float4 w4 = __ldg((const float4*)&We[cg * 4]);
    float4 at = __ldg((const float4*)&att[cg * 4]);

    float4 acc = make_float4(0.f, 0.f, 0.f, 0.f);
    float den = 0.f, easum = 0.f;

    for (int i = off + half; i < end; i += 2) {
        int2 ed = g_edges[i];
        int s = ed.x;
        float ea = __int_as_float(ed.y);
        easum += ea;
        uint2 u = *(const uint2*)&g_xlh[(size_t)s * 64 + cg * 4];
        float2 f01 = __half22float2(*(__half2*)&u.x);
        float2 f23 = __half22float2(*(__half2*)&u.y);
        float vx = f01.x + b.x + ea * w4.x;  vx = vx > 0.f ? vx : 0.2f * vx;
        float vy = f01.y + b.y + ea * w4.y;  vy = vy > 0.f ? vy : 0.2f * vy;
        float vz = f23.x + b.z + ea * w4.z;  vz = vz > 0.f ? vz : 0.2f * vz;
        float vw = f23.y + b.w + ea * w4.w;  vw = vw > 0.f ? vw : 0.2f * vw;
        float lg = vx * at.x + vy * at.y + vz * at.z + vw * at.w;
        lg += __shfl_xor_sync(m16, lg, 8);
        lg += __shfl_xor_sync(m16, lg, 4);
        lg += __shfl_xor_sync(m16, lg, 2);
        lg += __shfl_xor_sync(m16, lg, 1);
        float p = __expf(lg);
        den += p;
        acc.x += p * f01.x; acc.y += p * f01.y; acc.z += p * f23.x; acc.w += p * f23.y;
    }
    __syncwarp();
    acc.x += __shfl_xor_sync(0xffffffffu, acc.x, 16);
    acc.y += __shfl_xor_sync(0xffffffffu, acc.y, 16);
    acc.z += __shfl_xor_sync(0xffffffffu, acc.z, 16);
    acc.w += __shfl_xor_sync(0xffffffffu, acc.w, 16);
    den   += __shfl_xor_sync(0xffffffffu, den, 16);
    easum += __shfl_xor_sync(0xffffffffu, easum, 16);

    // self-loop edge: src = dst, ea = mean of incoming edge attrs
    {
        float lea = easum / fmaxf((float)cnt, 1.f);
        uint2 u = *(const uint2*)&g_xlh[(size_t)d * 64 + cg * 4];
        float2 f01 = __half22float2(*(__half2*)&u.x);
        float2 f23 = __half22float2(*(__half2*)&u.y);
        float vx = f01.x + b.x + lea * w4.x;  vx = vx > 0.f ? vx : 0.2f * vx;
        float vy = f01.y + b.y + lea * w4.y;  vy = vy > 0.f ? vy : 0.2f * vy;
        float vz = f23.x + b.z + lea * w4.z;  vz = vz > 0.f ? vz : 0.2f * vz;
        float vw = f23.y + b.w + lea * w4.w;  vw = vw > 0.f ? vw : 0.2f * vw;
        float lg = vx * at.x + vy * at.y + vz * at.z + vw * at.w;
        lg += __shfl_xor_sync(0xffffffffu, lg, 8);
        lg += __shfl_xor_sync(0xffffffffu, lg, 4);
        lg += __shfl_xor_sync(0xffffffffu, lg, 2);
        lg += __shfl_xor_sync(0xffffffffu, lg, 1);
        float p = __expf(lg);
        den += p;
        acc.x += p * f01.x; acc.y += p * f01.y; acc.z += p * f23.x; acc.w += p * f23.y;
    }

    float inv = 1.f / (den + 1e-16f);
    float4 bias4 = __ldg((const float4*)&bias[cg * 4]);
    float h0 = acc.x * inv + bias4.x;  h0 = h0 > 0.f ? h0 : expm1f(h0);
    float h1 = acc.y * inv + bias4.y;  h1 = h1 > 0.f ? h1 : expm1f(h1);
    float h2 = acc.z * inv + bias4.z;  h2 = h2 > 0.f ? h2 : expm1f(h2);
    float h3 = acc.w * inv + bias4.w;  h3 = h3 > 0.f ? h3 : expm1f(h3);

    if (half == 0) {
        if (LAYER == 0) {
            *(float4*)&g_h1[(size_t)d * 64 + cg * 4] = make_float4(h0, h1, h2, h3);
        } else {
            int g = batch[d];
            float* ptr = &g_gsum[g * 64 + cg * 4];
            asm volatile("red.global.add.v4.f32 [%0], {%1, %2, %3, %4};"
                         :: "l"(ptr), "f"(h0), "f"(h1), "f"(h2), "f"(h3)
                         : "memory");
            if (cg == 0) atomicAdd(&g_gcnt[g], 1.f);
        }
    }
}

// ---------------- head: relu(fc1) -> BN(eval) -> fc3 ----------------
__global__ void k_head(const float* __restrict__ Wfc1, const float* __restrict__ bfc1,
                       const float* __restrict__ gamma, const float* __restrict__ beta,
                       const float* __restrict__ mean, const float* __restrict__ var,
                       const float* __restrict__ Wfc3, const float* __restrict__ bfc3,
                       float* __restrict__ out) {
    int g = threadIdx.x;
    if (g >= GG) return;
    float cnt = fmaxf(g_gcnt[g], 1.f);
    float pooled[64];
#pragma unroll
    for (int c = 0; c < 64; c++) pooled[c] = g_gsum[g * 64 + c] / cnt;
    float acc = bfc3[0];
    for (int j = 0; j < 32; j++) {
        float z = bfc1[j];
#pragma unroll
        for (int c = 0; c < 64; c++) z = fmaf(pooled[c], Wfc1[c * 32 + j], z);
        z = fmaxf(z, 0.f);
        z = (z - mean[j]) * rsqrtf(var[j] + 1e-5f) * gamma[j] + beta[j];
        acc = fmaf(z, Wfc3[j], acc);
    }
    out[g] = acc;
}

// ---------------- launch ----------------
extern "C" void kernel_launch(void* const* d_in, const int* in_sizes, int n_in,
                              void* d_out, int out_size) {
    const float* x      = (const float*)d_in[0];
    const int*   eidx   = (const int*)d_in[1];
    const float* eattr  = (const float*)d_in[2];
    const int*   batch  = (const int*)d_in[3];
    const float* Wl1 = (const float*)d_in[4];   const float* bl1 = (const float*)d_in[5];
    const float* Wr1 = (const float*)d_in[6];   const float* br1 = (const float*)d_in[7];
    const float* We1 = (const float*)d_in[8];   const float* att1 = (const float*)d_in[9];
    const float* bias1 = (const float*)d_in[10];
    const float* Wl2 = (const float*)d_in[11];  const float* bl2 = (const float*)d_in[12];
    const float* Wr2 = (const float*)d_in[13];  const float* br2 = (const float*)d_in[14];
    const float* We2 = (const float*)d_in[15];  const float* att2 = (const float*)d_in[16];
    const float* bias2 = (const float*)d_in[17];
    const float* Wfc1 = (const float*)d_in[18]; const float* bfc1 = (const float*)d_in[19];
    const float* gamma = (const float*)d_in[20]; const float* beta = (const float*)d_in[21];
    const float* mean = (const float*)d_in[22];  const float* var = (const float*)d_in[23];
    const float* Wfc3 = (const float*)d_in[24];  const float* bfc3 = (const float*)d_in[25];
    float* out = (float*)d_out;

    const int* e_src = eidx;        // edge_index[0]
    const int* e_dst = eidx + EE;   // edge_index[1]

    const int TB = 256;
    const int nBlocksN    = (NN + TB - 1) / TB;
    const int nBlocksE    = (EE + TB - 1) / TB;
    const int nBlocksGemm = (NN + 63) / 64;
    const int nBlocksWarp = (NN * 32 + TB - 1) / TB;    // warp per dst

    const int smem1 = (2 * 128 * 64 + 64 * 128) * 4;    // 96 KB
    const int smem2 = (2 * 64 * 64 + 64 * 64) * 4;      // 48 KB
    cudaFuncSetAttribute(k_gemm2<128, 0>, cudaFuncAttributeMaxDynamicSharedMemorySize, smem1);
    cudaFuncSetAttribute(k_gemm2<64, 1>,  cudaFuncAttributeMaxDynamicSharedMemorySize, smem2);

    // ---- CSR build (once; reused by both layers) ----
    k_init0<<<nBlocksN, TB>>>();
    k_hist<<<nBlocksE, TB>>>(e_dst);
    k_scan1<<<NB, 512>>>();
    k_scan3<<<NB, 512>>>();
    k_escatter<<<nBlocksE, TB>>>(e_src, e_dst, eattr);

    // ---- layer 1 ----
    k_gemm2<128, 0><<<nBlocksGemm, TB, smem1>>>(x, Wl1, bl1, Wr1, br1);
    k_edge_sorted<0><<<nBlocksWarp, TB>>>(We1, att1, bias1, nullptr);   // -> g_h1

    // ---- layer 2 ----
    k_gemm2<64, 1><<<nBlocksGemm, TB, smem2>>>(nullptr, Wl2, bl2, Wr2, br2);
    k_edge_sorted<1><<<nBlocksWarp, TB>>>(We2, att2, bias2, batch);     // -> pool

    // ---- head ----
    k_head<<<1, 64>>>(Wfc1, bfc1, gamma, beta, mean, var, Wfc3, bfc3, out);
}